// round 6
// baseline (speedup 1.0000x reference)
#include <cuda_runtime.h>

#define N_NODES 10000
#define N_EDGES 320000
#define DIM 64

// Scratch (allocation-free rule: __device__ globals)
__device__ int   g_is32;                // 1 if edge_index buffer is int32
__device__ float g_deg[N_NODES];
__device__ float g_dinv[N_NODES];
__device__ float g_hs[N_NODES * DIM];   // (z@W)[i] * dinv[i]
__device__ float g_s[N_NODES * DIM];    // scatter accumulator
__device__ float g_zr[N_NODES * DIM];   // relu output

// ---------------------------------------------------------------- dtype probe
// If the buffer really is int64, every value lies in [0, N_NODES). If it is
// int32 read as int64, values fuse two indices -> astronomically large.
__global__ void detect_kernel(const long long* __restrict__ ei) {
    if (threadIdx.x == 0 && blockIdx.x == 0) {
        int bad = 0;
        for (int i = 0; i < 256; i++) {
            long long v = ei[i];
            if (v < 0 || v >= N_NODES) bad = 1;
        }
        g_is32 = bad;
    }
}

__device__ __forceinline__ int edge_fetch(const void* ei, int idx) {
    return g_is32 ? ((const int*)ei)[idx] : (int)((const long long*)ei)[idx];
}

// ---------------------------------------------------------------- init
__global__ void init_kernel() {
    int i = blockIdx.x * 256 + threadIdx.x;
    if (i < N_NODES * DIM) g_s[i] = 0.0f;
    if (i < N_NODES) g_deg[i] = 1.0f;   // self-loop contributes 1 to degree
}

// ---------------------------------------------------------------- degree
__global__ void deg_kernel(const void* __restrict__ ei) {
    int e = blockIdx.x * 256 + threadIdx.x;
    if (e < N_EDGES) {
        int col = edge_fetch(ei, N_EDGES + e);
        if ((unsigned)col < N_NODES) atomicAdd(&g_deg[col], 1.0f);
    }
}

__global__ void dinv_kernel() {
    int i = blockIdx.x * 256 + threadIdx.x;
    if (i < N_NODES) g_dinv[i] = rsqrtf(g_deg[i]);
}

// ---------------------------------------------------------------- hs = (z@W) * dinv
__global__ void hs_kernel(const float* __restrict__ z, const float* __restrict__ W) {
    __shared__ float Ws[DIM * DIM];
    __shared__ float zrow[4][DIM];
    int tid = threadIdx.x;                       // 256 threads
    for (int i = tid; i < DIM * DIM; i += 256) Ws[i] = W[i];
    int r = tid >> 6, d = tid & 63;
    int row = blockIdx.x * 4 + r;
    if (row < N_NODES) zrow[r][d] = z[row * DIM + d];
    __syncthreads();
    if (row < N_NODES) {
        float acc = 0.0f;
#pragma unroll
        for (int k = 0; k < DIM; k++) acc = fmaf(zrow[r][k], Ws[k * DIM + d], acc);
        g_hs[row * DIM + d] = acc * g_dinv[row];
    }
}

// ---------------------------------------------------------------- scatter: s[col] += hs[row]
__global__ void scatter_kernel(const void* __restrict__ ei) {
    unsigned idx = blockIdx.x * 256 + threadIdx.x;   // grid sized exactly E*64/256
    int e = idx >> 6;
    int d = idx & 63;
    int row = edge_fetch(ei, e);
    int col = edge_fetch(ei, N_EDGES + e);
    if ((unsigned)row < N_NODES && (unsigned)col < N_NODES)
        atomicAdd(&g_s[col * DIM + d], g_hs[row * DIM + d]);
}

// ---------------------------------------------------------------- zr = relu(dinv*(s+hs)+b)
__global__ void zr_kernel(const float* __restrict__ b) {
    int idx = blockIdx.x * 256 + threadIdx.x;
    if (idx < N_NODES * DIM) {
        int i = idx >> 6, d = idx & 63;
        float v = fmaf(g_dinv[i], g_s[idx] + g_hs[idx], b[d]);
        g_zr[idx] = fmaxf(v, 0.0f);
    }
}

// ---------------------------------------------------------------- C = zr @ zr.T (symmetric)
// 128x128 block tile, K=64 in two 32-k passes, STATIC 32KB smem.
// k-major tiles, interleaved 8x8 micro-tiles.
// Computes only bx >= by; mirrors each off-diagonal tile into the lower triangle.
__global__ __launch_bounds__(256) void gemm_kernel(float* __restrict__ C) {
    int bx = blockIdx.x, by = blockIdx.y;
    if (bx < by) return;

    __shared__ float As[32][128];   // As[k][m]
    __shared__ float Bs[32][128];   // Bs[k][n]

    int tid = threadIdx.x;
    int warp = tid >> 5, lane = tid & 31;
    int wm = warp >> 2, wn = warp & 3;
    int r = lane >> 2, c = lane & 3;

    float acc[8][8];
#pragma unroll
    for (int i = 0; i < 8; i++)
#pragma unroll
        for (int j = 0; j < 8; j++) acc[i][j] = 0.0f;

    int sa0 = (wm * 16 + r) * 4;       // m = wm*64 + r*4 + {0..3}
    int sa1 = (wm * 16 + 8 + r) * 4;   // m = wm*64 + 32 + r*4 + {0..3}
    int sb0 = (wn * 8 + c) * 4;        // n = wn*32 + c*4 + {0..3}
    int sb1 = (wn * 8 + 4 + c) * 4;    // n = wn*32 + 16 + c*4 + {0..3}

    // fill role: threads 0..127 own A-row tid, threads 128..255 own B-row tid-128
    int frow = tid & 127;
    bool isA = tid < 128;
    int grow = (isA ? by : bx) * 128 + frow;
    bool valid = grow < N_NODES;

#pragma unroll
    for (int kp = 0; kp < 2; kp++) {
        // ---- fill this k-half (k = kp*32 .. kp*32+31)
        float (*T)[128] = isA ? As : Bs;
#pragma unroll
        for (int i = 0; i < 8; i++) {
            float4 v = valid ? *(const float4*)&g_zr[grow * DIM + kp * 32 + i * 4]
                             : make_float4(0.f, 0.f, 0.f, 0.f);
            T[i * 4 + 0][frow] = v.x;
            T[i * 4 + 1][frow] = v.y;
            T[i * 4 + 2][frow] = v.z;
            T[i * 4 + 3][frow] = v.w;
        }
        __syncthreads();

        // ---- compute 32 k-steps
#pragma unroll 4
        for (int k = 0; k < 32; k++) {
            float4 a0 = *(const float4*)(&As[k][0] + sa0);
            float4 a1 = *(const float4*)(&As[k][0] + sa1);
            float4 b0 = *(const float4*)(&Bs[k][0] + sb0);
            float4 b1 = *(const float4*)(&Bs[k][0] + sb1);
            float av[8] = {a0.x, a0.y, a0.z, a0.w, a1.x, a1.y, a1.z, a1.w};
            float bv[8] = {b0.x, b0.y, b0.z, b0.w, b1.x, b1.y, b1.z, b1.w};
#pragma unroll
            for (int i = 0; i < 8; i++)
#pragma unroll
                for (int j = 0; j < 8; j++)
                    acc[i][j] = fmaf(av[i], bv[j], acc[i][j]);
        }
        __syncthreads();
    }

    // --- store upper tile (row-major)
    int m0g[2] = {by * 128 + wm * 64 + r * 4, by * 128 + wm * 64 + 32 + r * 4};
    int n0g[2] = {bx * 128 + wn * 32 + c * 4, bx * 128 + wn * 32 + 16 + c * 4};
#pragma unroll
    for (int ig = 0; ig < 2; ig++)
#pragma unroll
        for (int ii = 0; ii < 4; ii++) {
            int m = m0g[ig] + ii;
            if (m < N_NODES) {
#pragma unroll
                for (int jg = 0; jg < 2; jg++) {
                    int n = n0g[jg];
                    if (n < N_NODES) {   // n multiple of 4, N_NODES multiple of 4 => n+3 safe
                        float4 v = make_float4(acc[ig * 4 + ii][jg * 4 + 0],
                                               acc[ig * 4 + ii][jg * 4 + 1],
                                               acc[ig * 4 + ii][jg * 4 + 2],
                                               acc[ig * 4 + ii][jg * 4 + 3]);
                        *(float4*)&C[(size_t)m * N_NODES + n] = v;
                    }
                }
            }
        }

    // --- mirror into lower triangle (transpose store, float4 along m)
    if (bx != by) {
#pragma unroll
        for (int jg = 0; jg < 2; jg++)
#pragma unroll
            for (int jj = 0; jj < 4; jj++) {
                int n = n0g[jg] + jj;
                if (n < N_NODES) {
#pragma unroll
                    for (int ig = 0; ig < 2; ig++) {
                        int m = m0g[ig];
                        if (m < N_NODES) {
                            float4 v = make_float4(acc[ig * 4 + 0][jg * 4 + jj],
                                                   acc[ig * 4 + 1][jg * 4 + jj],
                                                   acc[ig * 4 + 2][jg * 4 + jj],
                                                   acc[ig * 4 + 3][jg * 4 + jj]);
                            *(float4*)&C[(size_t)n * N_NODES + m] = v;
                        }
                    }
                }
            }
    }
}

// ---------------------------------------------------------------- launch
extern "C" void kernel_launch(void* const* d_in, const int* in_sizes, int n_in,
                              void* d_out, int out_size) {
    const float* z = (const float*)d_in[0];
    const void* ei = d_in[1];
    const float* W = (const float*)d_in[2];
    const float* b = (const float*)d_in[3];
    float* C = (float*)d_out;

    detect_kernel<<<1, 32>>>((const long long*)ei);
    init_kernel<<<(N_NODES * DIM + 255) / 256, 256>>>();
    deg_kernel<<<(N_EDGES + 255) / 256, 256>>>(ei);
    dinv_kernel<<<(N_NODES + 255) / 256, 256>>>();
    hs_kernel<<<(N_NODES + 3) / 4, 256>>>(z, W);
    scatter_kernel<<<(N_EDGES * DIM) / 256, 256>>>(ei);
    zr_kernel<<<(N_NODES * DIM + 255) / 256, 256>>>(b);

    dim3 grid(79, 79);
    gemm_kernel<<<grid, 256>>>(C);
}

// round 9
// speedup vs baseline: 1.0499x; 1.0499x over previous
#include <cuda_runtime.h>
#include <cuda_bf16.h>
#include <cstdint>

#define N_NODES 10000
#define N_PAD 10112           // 79 * 128
#define N_EDGES 320000
#define DIM 64
#define NTILE 79

// Scratch (allocation-free rule: __device__ globals)
__device__ int   g_is32;
__device__ float g_deg[N_NODES];
__device__ float g_dinv[N_NODES];
__device__ float g_hs[N_NODES * DIM];
__device__ float g_s[N_NODES * DIM];
__device__ __nv_bfloat16 g_zrh[N_PAD * DIM];   // bf16 hi plane of zr (padded)
__device__ __nv_bfloat16 g_zrl[N_PAD * DIM];   // bf16 lo plane of zr (padded)

// ---------------------------------------------------------------- dtype probe
__global__ void detect_kernel(const long long* __restrict__ ei) {
    if (threadIdx.x == 0 && blockIdx.x == 0) {
        int bad = 0;
        for (int i = 0; i < 256; i++) {
            long long v = ei[i];
            if (v < 0 || v >= N_NODES) bad = 1;
        }
        g_is32 = bad;
    }
}
__device__ __forceinline__ int edge_fetch(const void* ei, int idx) {
    return g_is32 ? ((const int*)ei)[idx] : (int)((const long long*)ei)[idx];
}

// ---------------------------------------------------------------- init
__global__ void init_kernel() {
    int i = blockIdx.x * 256 + threadIdx.x;
    if (i < N_NODES * DIM) g_s[i] = 0.0f;
    if (i < N_NODES) g_deg[i] = 1.0f;
    if (i < (N_PAD - N_NODES) * DIM) {
        g_zrh[N_NODES * DIM + i] = __float2bfloat16(0.0f);
        g_zrl[N_NODES * DIM + i] = __float2bfloat16(0.0f);
    }
}

// ---------------------------------------------------------------- degree
__global__ void deg_kernel(const void* __restrict__ ei) {
    int e = blockIdx.x * 256 + threadIdx.x;
    if (e < N_EDGES) {
        int col = edge_fetch(ei, N_EDGES + e);
        if ((unsigned)col < N_NODES) atomicAdd(&g_deg[col], 1.0f);
    }
}
__global__ void dinv_kernel() {
    int i = blockIdx.x * 256 + threadIdx.x;
    if (i < N_NODES) g_dinv[i] = rsqrtf(g_deg[i]);
}

// ---------------------------------------------------------------- hs = (z@W) * dinv
__global__ void hs_kernel(const float* __restrict__ z, const float* __restrict__ W) {
    __shared__ float Ws[DIM * DIM];
    __shared__ float zrow[4][DIM];
    int tid = threadIdx.x;
    for (int i = tid; i < DIM * DIM; i += 256) Ws[i] = W[i];
    int r = tid >> 6, d = tid & 63;
    int row = blockIdx.x * 4 + r;
    if (row < N_NODES) zrow[r][d] = z[row * DIM + d];
    __syncthreads();
    if (row < N_NODES) {
        float acc = 0.0f;
#pragma unroll
        for (int k = 0; k < DIM; k++) acc = fmaf(zrow[r][k], Ws[k * DIM + d], acc);
        g_hs[row * DIM + d] = acc * g_dinv[row];
    }
}

// ---------------------------------------------------------------- scatter
__global__ void scatter_kernel(const void* __restrict__ ei) {
    unsigned idx = blockIdx.x * 256 + threadIdx.x;
    int e = idx >> 6;
    int d = idx & 63;
    int row = edge_fetch(ei, e);
    int col = edge_fetch(ei, N_EDGES + e);
    if ((unsigned)row < N_NODES && (unsigned)col < N_NODES)
        atomicAdd(&g_s[col * DIM + d], g_hs[row * DIM + d]);
}

// ---------------------------------------------------------------- zr = relu(...); split bf16 hi/lo
__global__ void zr_kernel(const float* __restrict__ b) {
    int idx = blockIdx.x * 256 + threadIdx.x;
    if (idx < N_NODES * DIM) {
        int i = idx >> 6, d = idx & 63;
        float v = fmaf(g_dinv[i], g_s[idx] + g_hs[idx], b[d]);
        v = fmaxf(v, 0.0f);
        __nv_bfloat16 hi = __float2bfloat16(v);
        float lo = v - __bfloat162float(hi);
        g_zrh[idx] = hi;
        g_zrl[idx] = __float2bfloat16(lo);
    }
}

// ---------------------------------------------------------------- mma.sync GEMM: C = zr @ zr.T
// C ~= Ahi*Bhi^T + Ahi*Blo^T + Alo*Bhi^T, fp32 accum in registers.
// 128x128 tile per CTA, triangular grid (by <= bx), mirror store for lower half.
// K=64 in two 32-k passes; smem tiles [128][36] bf16 (pad -> conflict-free).

#define MMA16816(d, a0, a1, a2, a3, b0, b1)                                     \
    asm volatile(                                                               \
        "mma.sync.aligned.m16n8k16.row.col.f32.bf16.bf16.f32 "                  \
        "{%0,%1,%2,%3},{%4,%5,%6,%7},{%8,%9},{%0,%1,%2,%3};"                    \
        : "+f"(d[0]), "+f"(d[1]), "+f"(d[2]), "+f"(d[3])                        \
        : "r"(a0), "r"(a1), "r"(a2), "r"(a3), "r"(b0), "r"(b1))

__global__ __launch_bounds__(256) void gemm_mma_kernel(float* __restrict__ C) {
    // triangular index -> (bx, by), by <= bx
    int i = blockIdx.x;
    int bx = (int)((sqrtf(8.0f * i + 1.0f) - 1.0f) * 0.5f);
    while ((bx + 1) * (bx + 2) / 2 <= i) bx++;
    while (bx * (bx + 1) / 2 > i) bx--;
    int by = i - bx * (bx + 1) / 2;

    __shared__ __align__(16) __nv_bfloat16 Ah[128][36];
    __shared__ __align__(16) __nv_bfloat16 Al[128][36];
    __shared__ __align__(16) __nv_bfloat16 Bh[128][36];
    __shared__ __align__(16) __nv_bfloat16 Bl[128][36];

    int tid = threadIdx.x;
    int wid = tid >> 5, lane = tid & 31;
    int wm = wid >> 2, wn = wid & 3;        // warp tile: 64m x 32n
    int g = lane >> 2, t = lane & 3;

    float acc[4][4][4];                      // [mi][ni][reg]
#pragma unroll
    for (int mi = 0; mi < 4; mi++)
#pragma unroll
        for (int ni = 0; ni < 4; ni++)
#pragma unroll
            for (int r = 0; r < 4; r++) acc[mi][ni][r] = 0.0f;

    // fill roles
    int frow = tid & 127;
    bool isA = tid < 128;
    int grow = (isA ? by : bx) * 128 + frow;          // < N_PAD
    __nv_bfloat16* dsth = isA ? &Ah[frow][0] : &Bh[frow][0];
    __nv_bfloat16* dstl = isA ? &Al[frow][0] : &Bl[frow][0];

#pragma unroll
    for (int kp = 0; kp < 2; kp++) {
        if (kp) __syncthreads();   // protect previous pass tiles
        // ---- fill 32 k-columns of hi & lo
        {
            const uint2* sh = (const uint2*)&g_zrh[grow * DIM + kp * 32];
            const uint2* sl = (const uint2*)&g_zrl[grow * DIM + kp * 32];
#pragma unroll
            for (int c = 0; c < 8; c++) {
                *(uint2*)&dsth[c * 4] = sh[c];
                *(uint2*)&dstl[c * 4] = sl[c];
            }
        }
        __syncthreads();

        // ---- 2 k16-steps per pass, 3 products each
#pragma unroll
        for (int ks = 0; ks < 2; ks++) {
            int k0 = ks * 16 + 2 * t;
            uint32_t ah[4][4], al[4][4], bh[4][2], bl[4][2];
#pragma unroll
            for (int mi = 0; mi < 4; mi++) {
                int r0 = wm * 64 + mi * 16 + g;
                ah[mi][0] = *(const uint32_t*)&Ah[r0][k0];
                ah[mi][1] = *(const uint32_t*)&Ah[r0 + 8][k0];
                ah[mi][2] = *(const uint32_t*)&Ah[r0][k0 + 8];
                ah[mi][3] = *(const uint32_t*)&Ah[r0 + 8][k0 + 8];
                al[mi][0] = *(const uint32_t*)&Al[r0][k0];
                al[mi][1] = *(const uint32_t*)&Al[r0 + 8][k0];
                al[mi][2] = *(const uint32_t*)&Al[r0][k0 + 8];
                al[mi][3] = *(const uint32_t*)&Al[r0 + 8][k0 + 8];
            }
#pragma unroll
            for (int ni = 0; ni < 4; ni++) {
                int c0 = wn * 32 + ni * 8 + g;
                bh[ni][0] = *(const uint32_t*)&Bh[c0][k0];
                bh[ni][1] = *(const uint32_t*)&Bh[c0][k0 + 8];
                bl[ni][0] = *(const uint32_t*)&Bl[c0][k0];
                bl[ni][1] = *(const uint32_t*)&Bl[c0][k0 + 8];
            }
#pragma unroll
            for (int mi = 0; mi < 4; mi++)
#pragma unroll
                for (int ni = 0; ni < 4; ni++) {
                    MMA16816(acc[mi][ni], ah[mi][0], ah[mi][1], ah[mi][2], ah[mi][3],
                             bh[ni][0], bh[ni][1]);
                    MMA16816(acc[mi][ni], ah[mi][0], ah[mi][1], ah[mi][2], ah[mi][3],
                             bl[ni][0], bl[ni][1]);
                    MMA16816(acc[mi][ni], al[mi][0], al[mi][1], al[mi][2], al[mi][3],
                             bh[ni][0], bh[ni][1]);
                }
        }
    }

    // ---- epilogue
    bool diag = (bx == by);
#pragma unroll
    for (int mi = 0; mi < 4; mi++) {
        int m0 = by * 128 + wm * 64 + mi * 16 + g;   // and m0+8
#pragma unroll
        for (int ni = 0; ni < 4; ni++) {
            int n0 = bx * 128 + wn * 32 + ni * 8 + 2 * t;  // even
            float* a = acc[mi][ni];
            if (n0 < N_NODES) {
                if (m0 < N_NODES)
                    *(float2*)&C[(size_t)m0 * N_NODES + n0] = make_float2(a[0], a[1]);
                if (m0 + 8 < N_NODES)
                    *(float2*)&C[(size_t)(m0 + 8) * N_NODES + n0] = make_float2(a[2], a[3]);
            }
            if (!diag) {   // mirror: C[n][m]
                if (n0 < N_NODES) {
                    if (m0 < N_NODES)     C[(size_t)n0 * N_NODES + m0] = a[0];
                    if (m0 + 8 < N_NODES) C[(size_t)n0 * N_NODES + m0 + 8] = a[2];
                }
                if (n0 + 1 < N_NODES) {
                    if (m0 < N_NODES)     C[(size_t)(n0 + 1) * N_NODES + m0] = a[1];
                    if (m0 + 8 < N_NODES) C[(size_t)(n0 + 1) * N_NODES + m0 + 8] = a[3];
                }
            }
        }
    }
}

// ---------------------------------------------------------------- launch
extern "C" void kernel_launch(void* const* d_in, const int* in_sizes, int n_in,
                              void* d_out, int out_size) {
    const float* z = (const float*)d_in[0];
    const void* ei = d_in[1];
    const float* W = (const float*)d_in[2];
    const float* b = (const float*)d_in[3];
    float* C = (float*)d_out;

    detect_kernel<<<1, 32>>>((const long long*)ei);
    init_kernel<<<(N_NODES * DIM + 255) / 256, 256>>>();
    deg_kernel<<<(N_EDGES + 255) / 256, 256>>>(ei);
    dinv_kernel<<<(N_NODES + 255) / 256, 256>>>();
    hs_kernel<<<(N_NODES + 3) / 4, 256>>>(z, W);
    scatter_kernel<<<(N_EDGES * DIM) / 256, 256>>>(ei);
    zr_kernel<<<(N_NODES * DIM + 255) / 256, 256>>>(b);

    gemm_mma_kernel<<<NTILE * (NTILE + 1) / 2, 256>>>(C);
}

// round 11
// speedup vs baseline: 1.1890x; 1.1325x over previous
#include <cuda_runtime.h>
#include <cuda_bf16.h>
#include <cstdint>

#define N_NODES 10000
#define N_PAD 10112           // 79 * 128
#define N_EDGES 320000
#define DIM 64
#define NTILE 79

// Scratch (allocation-free rule: __device__ globals)
__device__ int   g_is32;
__device__ int   g_cnt[N_NODES];        // incoming-edge histogram (no self-loop)
__device__ int   g_cursor[N_NODES];
__device__ int   g_off[N_NODES + 1];
__device__ int   g_bucket[N_EDGES];     // source rows grouped by destination
__device__ float g_dinv[N_NODES];
__device__ float g_hs[N_NODES * DIM];
__device__ __nv_bfloat16 g_zrh[N_PAD * DIM];   // bf16 hi plane of zr (padded)
__device__ __nv_bfloat16 g_zrl[N_PAD * DIM];   // bf16 lo plane of zr (padded)

// ---------------------------------------------------------------- dtype probe (parallel)
__global__ void detect_kernel(const long long* __restrict__ ei) {
    __shared__ unsigned wm[8];
    int t = threadIdx.x;                 // 256 threads
    long long v = ei[t];
    int bad = (v < 0 || v >= N_NODES) ? 1 : 0;
    unsigned m = __ballot_sync(0xFFFFFFFFu, bad);
    if ((t & 31) == 0) wm[t >> 5] = m;
    __syncthreads();
    if (t == 0) {
        unsigned any = 0;
#pragma unroll
        for (int i = 0; i < 8; i++) any |= wm[i];
        g_is32 = any ? 1 : 0;
    }
}
__device__ __forceinline__ int edge_fetch(const void* ei, int idx) {
    return g_is32 ? ((const int*)ei)[idx] : (int)((const long long*)ei)[idx];
}

// ---------------------------------------------------------------- init
__global__ void init_kernel() {
    int i = blockIdx.x * 256 + threadIdx.x;
    if (i < N_NODES) { g_cnt[i] = 0; g_cursor[i] = 0; }
    if (i < (N_PAD - N_NODES) * DIM) {
        g_zrh[N_NODES * DIM + i] = __float2bfloat16(0.0f);
        g_zrl[N_NODES * DIM + i] = __float2bfloat16(0.0f);
    }
}

// ---------------------------------------------------------------- histogram of destinations
__global__ void hist_kernel(const void* __restrict__ ei) {
    int e = blockIdx.x * 256 + threadIdx.x;
    if (e < N_EDGES) {
        int col = edge_fetch(ei, N_EDGES + e);
        if ((unsigned)col < N_NODES) atomicAdd(&g_cnt[col], 1);
    }
}

// ---------------------------------------------------------------- scan: offsets + dinv
__global__ void scan_kernel() {
    __shared__ int part[1024];
    int t = threadIdx.x;                  // 1024 threads, 1 block
    const int CH = 10;                    // 1024*10 >= 10000
    int base = t * CH;
    int loc[CH];
    int s = 0;
#pragma unroll
    for (int j = 0; j < CH; j++) {
        int idx = base + j;
        loc[j] = s;
        s += (idx < N_NODES) ? g_cnt[idx] : 0;
    }
    part[t] = s;
    __syncthreads();
    for (int off = 1; off < 1024; off <<= 1) {
        int v = (t >= off) ? part[t - off] : 0;
        __syncthreads();
        part[t] += v;
        __syncthreads();
    }
    int excl = part[t] - s;
#pragma unroll
    for (int j = 0; j < CH; j++) {
        int idx = base + j;
        if (idx < N_NODES) {
            g_off[idx] = excl + loc[j];
            g_dinv[idx] = rsqrtf((float)(g_cnt[idx] + 1));   // +1 self loop
        }
    }
    if (t == 1023) g_off[N_NODES] = part[1023];
}

// ---------------------------------------------------------------- hs = (z@W) * dinv
__global__ void hs_kernel(const float* __restrict__ z, const float* __restrict__ W) {
    __shared__ float Ws[DIM * DIM];
    __shared__ float zrow[4][DIM];
    int tid = threadIdx.x;
    for (int i = tid; i < DIM * DIM; i += 256) Ws[i] = W[i];
    int r = tid >> 6, d = tid & 63;
    int row = blockIdx.x * 4 + r;
    if (row < N_NODES) zrow[r][d] = z[row * DIM + d];
    __syncthreads();
    if (row < N_NODES) {
        float acc = 0.0f;
#pragma unroll
        for (int k = 0; k < DIM; k++) acc = fmaf(zrow[r][k], Ws[k * DIM + d], acc);
        g_hs[row * DIM + d] = acc * g_dinv[row];
    }
}

// ---------------------------------------------------------------- bucket fill (CSR)
__global__ void fill_kernel(const void* __restrict__ ei) {
    int e = blockIdx.x * 256 + threadIdx.x;
    if (e < N_EDGES) {
        int row = edge_fetch(ei, e);
        int col = edge_fetch(ei, N_EDGES + e);
        if ((unsigned)row < N_NODES && (unsigned)col < N_NODES) {
            int pos = atomicAdd(&g_cursor[col], 1);
            g_bucket[g_off[col] + pos] = row;
        }
    }
}

// ---------------------------------------------------------------- gather + zr fused
// 4 nodes per 256-thread block; 64 threads own one node's 64 dims.
__global__ void gather_zr_kernel(const float* __restrict__ b) {
    int tid = threadIdx.x;
    int node = blockIdx.x * 4 + (tid >> 6);
    int d = tid & 63;
    if (node >= N_NODES) return;
    int off0 = g_off[node], off1 = g_off[node + 1];
    float acc = 0.0f;
    int k = off0;
    for (; k + 4 <= off1; k += 4) {
        int r0 = g_bucket[k], r1 = g_bucket[k + 1];
        int r2 = g_bucket[k + 2], r3 = g_bucket[k + 3];
        acc += g_hs[r0 * DIM + d] + g_hs[r1 * DIM + d]
             + g_hs[r2 * DIM + d] + g_hs[r3 * DIM + d];
    }
    for (; k < off1; k++) acc += g_hs[g_bucket[k] * DIM + d];

    int idx = node * DIM + d;
    float v = fmaf(g_dinv[node], acc + g_hs[idx], b[d]);
    v = fmaxf(v, 0.0f);
    __nv_bfloat16 hi = __float2bfloat16(v);
    float lo = v - __bfloat162float(hi);
    g_zrh[idx] = hi;
    g_zrl[idx] = __float2bfloat16(lo);
}

// ---------------------------------------------------------------- mma.sync GEMM: C = zr @ zr.T
#define MMA16816(d, a0, a1, a2, a3, b0, b1)                                     \
    asm volatile(                                                               \
        "mma.sync.aligned.m16n8k16.row.col.f32.bf16.bf16.f32 "                  \
        "{%0,%1,%2,%3},{%4,%5,%6,%7},{%8,%9},{%0,%1,%2,%3};"                    \
        : "+f"(d[0]), "+f"(d[1]), "+f"(d[2]), "+f"(d[3])                        \
        : "r"(a0), "r"(a1), "r"(a2), "r"(a3), "r"(b0), "r"(b1))

__global__ __launch_bounds__(256) void gemm_mma_kernel(float* __restrict__ C) {
    int i = blockIdx.x;
    int bx = (int)((sqrtf(8.0f * i + 1.0f) - 1.0f) * 0.5f);
    while ((bx + 1) * (bx + 2) / 2 <= i) bx++;
    while (bx * (bx + 1) / 2 > i) bx--;
    int by = i - bx * (bx + 1) / 2;

    __shared__ __align__(16) __nv_bfloat16 Ah[128][36];
    __shared__ __align__(16) __nv_bfloat16 Al[128][36];
    __shared__ __align__(16) __nv_bfloat16 Bh[128][36];
    __shared__ __align__(16) __nv_bfloat16 Bl[128][36];

    int tid = threadIdx.x;
    int wid = tid >> 5, lane = tid & 31;
    int wm = wid >> 2, wn = wid & 3;
    int g = lane >> 2, t = lane & 3;

    float acc[4][4][4];
#pragma unroll
    for (int mi = 0; mi < 4; mi++)
#pragma unroll
        for (int ni = 0; ni < 4; ni++)
#pragma unroll
            for (int r = 0; r < 4; r++) acc[mi][ni][r] = 0.0f;

    int frow = tid & 127;
    bool isA = tid < 128;
    int grow = (isA ? by : bx) * 128 + frow;
    __nv_bfloat16* dsth = isA ? &Ah[frow][0] : &Bh[frow][0];
    __nv_bfloat16* dstl = isA ? &Al[frow][0] : &Bl[frow][0];

#pragma unroll
    for (int kp = 0; kp < 2; kp++) {
        if (kp) __syncthreads();
        {
            const uint2* sh = (const uint2*)&g_zrh[grow * DIM + kp * 32];
            const uint2* sl = (const uint2*)&g_zrl[grow * DIM + kp * 32];
#pragma unroll
            for (int c = 0; c < 8; c++) {
                *(uint2*)&dsth[c * 4] = sh[c];
                *(uint2*)&dstl[c * 4] = sl[c];
            }
        }
        __syncthreads();

#pragma unroll
        for (int ks = 0; ks < 2; ks++) {
            int k0 = ks * 16 + 2 * t;
            uint32_t ah[4][4], al[4][4], bh[4][2], bl[4][2];
#pragma unroll
            for (int mi = 0; mi < 4; mi++) {
                int r0 = wm * 64 + mi * 16 + g;
                ah[mi][0] = *(const uint32_t*)&Ah[r0][k0];
                ah[mi][1] = *(const uint32_t*)&Ah[r0 + 8][k0];
                ah[mi][2] = *(const uint32_t*)&Ah[r0][k0 + 8];
                ah[mi][3] = *(const uint32_t*)&Ah[r0 + 8][k0 + 8];
                al[mi][0] = *(const uint32_t*)&Al[r0][k0];
                al[mi][1] = *(const uint32_t*)&Al[r0 + 8][k0];
                al[mi][2] = *(const uint32_t*)&Al[r0][k0 + 8];
                al[mi][3] = *(const uint32_t*)&Al[r0 + 8][k0 + 8];
            }
#pragma unroll
            for (int ni = 0; ni < 4; ni++) {
                int c0 = wn * 32 + ni * 8 + g;
                bh[ni][0] = *(const uint32_t*)&Bh[c0][k0];
                bh[ni][1] = *(const uint32_t*)&Bh[c0][k0 + 8];
                bl[ni][0] = *(const uint32_t*)&Bl[c0][k0];
                bl[ni][1] = *(const uint32_t*)&Bl[c0][k0 + 8];
            }
#pragma unroll
            for (int mi = 0; mi < 4; mi++)
#pragma unroll
                for (int ni = 0; ni < 4; ni++) {
                    MMA16816(acc[mi][ni], ah[mi][0], ah[mi][1], ah[mi][2], ah[mi][3],
                             bh[ni][0], bh[ni][1]);
                    MMA16816(acc[mi][ni], ah[mi][0], ah[mi][1], ah[mi][2], ah[mi][3],
                             bl[ni][0], bl[ni][1]);
                    MMA16816(acc[mi][ni], al[mi][0], al[mi][1], al[mi][2], al[mi][3],
                             bh[ni][0], bh[ni][1]);
                }
        }
    }

    bool diag = (bx == by);
#pragma unroll
    for (int mi = 0; mi < 4; mi++) {
        int m0 = by * 128 + wm * 64 + mi * 16 + g;
#pragma unroll
        for (int ni = 0; ni < 4; ni++) {
            int n0 = bx * 128 + wn * 32 + ni * 8 + 2 * t;
            float* a = acc[mi][ni];
            if (n0 < N_NODES) {
                if (m0 < N_NODES)
                    *(float2*)&C[(size_t)m0 * N_NODES + n0] = make_float2(a[0], a[1]);
                if (m0 + 8 < N_NODES)
                    *(float2*)&C[(size_t)(m0 + 8) * N_NODES + n0] = make_float2(a[2], a[3]);
            }
            if (!diag) {
                if (n0 < N_NODES) {
                    if (m0 < N_NODES)     C[(size_t)n0 * N_NODES + m0] = a[0];
                    if (m0 + 8 < N_NODES) C[(size_t)n0 * N_NODES + m0 + 8] = a[2];
                }
                if (n0 + 1 < N_NODES) {
                    if (m0 < N_NODES)     C[(size_t)(n0 + 1) * N_NODES + m0] = a[1];
                    if (m0 + 8 < N_NODES) C[(size_t)(n0 + 1) * N_NODES + m0 + 8] = a[3];
                }
            }
        }
    }
}

// ---------------------------------------------------------------- launch
extern "C" void kernel_launch(void* const* d_in, const int* in_sizes, int n_in,
                              void* d_out, int out_size) {
    const float* z = (const float*)d_in[0];
    const void* ei = d_in[1];
    const float* W = (const float*)d_in[2];
    const float* b = (const float*)d_in[3];
    float* C = (float*)d_out;

    detect_kernel<<<1, 256>>>((const long long*)ei);
    init_kernel<<<(N_NODES * DIM + 255) / 256, 256>>>();
    hist_kernel<<<(N_EDGES + 255) / 256, 256>>>(ei);
    scan_kernel<<<1, 1024>>>();
    hs_kernel<<<(N_NODES + 3) / 4, 256>>>(z, W);
    fill_kernel<<<(N_EDGES + 255) / 256, 256>>>(ei);
    gather_zr_kernel<<<(N_NODES + 3) / 4, 256>>>(b);
    gemm_mma_kernel<<<NTILE * (NTILE + 1) / 2, 256>>>(C);
}

// round 13
// speedup vs baseline: 1.2652x; 1.0641x over previous
#include <cuda_runtime.h>
#include <cuda_bf16.h>
#include <cstdint>

#define N_NODES 10000
#define N_PAD 10112           // 79 * 128
#define N_EDGES 320000
#define DIM 64
#define NTILE 79

// Scratch (allocation-free rule: __device__ globals)
__device__ int   g_is32;
__device__ int   g_cnt[N_NODES];        // incoming-edge histogram (no self-loop)
__device__ int   g_cursor[N_NODES];
__device__ int   g_off[N_NODES + 4];    // +pad so int4 store at 9996 is safe
__device__ int   g_bucket[N_EDGES];     // source rows grouped by destination
__device__ float g_dinv[N_NODES];
__device__ float g_hs[N_NODES * DIM];
__device__ __nv_bfloat16 g_zrh[N_PAD * DIM];   // bf16 hi plane of zr (padded)
__device__ __nv_bfloat16 g_zrl[N_PAD * DIM];   // bf16 lo plane of zr (padded)

__device__ __forceinline__ int edge_fetch(const void* ei, int idx) {
    return g_is32 ? ((const int*)ei)[idx] : (int)((const long long*)ei)[idx];
}

// ---------------------------------------------------------------- init (+ dtype probe in block 0)
__global__ void init_kernel(const long long* __restrict__ ei) {
    int i = blockIdx.x * 256 + threadIdx.x;
    if (blockIdx.x == 0) {
        __shared__ unsigned wm[8];
        long long v = ei[threadIdx.x];
        int bad = (v < 0 || v >= N_NODES) ? 1 : 0;
        unsigned m = __ballot_sync(0xFFFFFFFFu, bad);
        if ((threadIdx.x & 31) == 0) wm[threadIdx.x >> 5] = m;
        __syncthreads();
        if (threadIdx.x == 0) {
            unsigned any = 0;
#pragma unroll
            for (int j = 0; j < 8; j++) any |= wm[j];
            g_is32 = any ? 1 : 0;
        }
    }
    if (i < N_NODES) { g_cnt[i] = 0; g_cursor[i] = 0; }
    if (i < (N_PAD - N_NODES) * DIM) {
        g_zrh[N_NODES * DIM + i] = __float2bfloat16(0.0f);
        g_zrl[N_NODES * DIM + i] = __float2bfloat16(0.0f);
    }
}

// ---------------------------------------------------------------- histogram of destinations
__global__ void hist_kernel(const void* __restrict__ ei) {
    int e = blockIdx.x * 256 + threadIdx.x;
    if (e < N_EDGES) {
        int col = edge_fetch(ei, N_EDGES + e);
        if ((unsigned)col < N_NODES) atomicAdd(&g_cnt[col], 1);
    }
}

// ---------------------------------------------------------------- scan: offsets + dinv (shfl-based)
__global__ void scan_kernel() {
    int t = threadIdx.x;                 // 256 threads, 1 block
    int lane = t & 31, w = t >> 5;
    const int CH = 40;                   // 256*40 = 10240 >= 10000 (10000 % 4 == 0)
    int base = t * CH;
    int4 c[10];
    int s = 0;
#pragma unroll
    for (int j = 0; j < 10; j++) {
        int idx = base + j * 4;
        c[j] = (idx < N_NODES) ? *(const int4*)&g_cnt[idx] : make_int4(0, 0, 0, 0);
        s += c[j].x + c[j].y + c[j].z + c[j].w;
    }
    // warp inclusive scan
    int v = s;
#pragma unroll
    for (int o = 1; o < 32; o <<= 1) {
        int u = __shfl_up_sync(0xFFFFFFFFu, v, o);
        if (lane >= o) v += u;
    }
    __shared__ int wsum[8];
    if (lane == 31) wsum[w] = v;
    __syncthreads();
    if (w == 0 && lane < 8) {
        int x = wsum[lane];
#pragma unroll
        for (int o = 1; o < 8; o <<= 1) {
            int u = __shfl_up_sync(0xFFu, x, o);
            if (lane >= o) x += u;
        }
        wsum[lane] = x;
    }
    __syncthreads();
    int excl = v - s + (w ? wsum[w - 1] : 0);
#pragma unroll
    for (int j = 0; j < 10; j++) {
        int idx = base + j * 4;
        if (idx < N_NODES) {
            int4 off;
            off.x = excl;
            off.y = off.x + c[j].x;
            off.z = off.y + c[j].y;
            off.w = off.z + c[j].z;
            excl = off.w + c[j].w;
            *(int4*)&g_off[idx] = off;
            g_dinv[idx]     = rsqrtf((float)(c[j].x + 1));
            g_dinv[idx + 1] = rsqrtf((float)(c[j].y + 1));
            g_dinv[idx + 2] = rsqrtf((float)(c[j].z + 1));
            g_dinv[idx + 3] = rsqrtf((float)(c[j].w + 1));
        }
    }
    if (t == 255) g_off[N_NODES] = excl;
}

// ---------------------------------------------------------------- hs = (z@W) * dinv
__global__ void hs_kernel(const float* __restrict__ z, const float* __restrict__ W) {
    __shared__ float Ws[DIM * DIM];
    __shared__ float zrow[4][DIM];
    int tid = threadIdx.x;
    for (int i = tid; i < DIM * DIM; i += 256) Ws[i] = W[i];
    int r = tid >> 6, d = tid & 63;
    int row = blockIdx.x * 4 + r;
    if (row < N_NODES) zrow[r][d] = z[row * DIM + d];
    __syncthreads();
    if (row < N_NODES) {
        float acc = 0.0f;
#pragma unroll
        for (int k = 0; k < DIM; k++) acc = fmaf(zrow[r][k], Ws[k * DIM + d], acc);
        g_hs[row * DIM + d] = acc * g_dinv[row];
    }
}

// ---------------------------------------------------------------- bucket fill (CSR)
__global__ void fill_kernel(const void* __restrict__ ei) {
    int e = blockIdx.x * 256 + threadIdx.x;
    if (e < N_EDGES) {
        int row = edge_fetch(ei, e);
        int col = edge_fetch(ei, N_EDGES + e);
        if ((unsigned)row < N_NODES && (unsigned)col < N_NODES) {
            int pos = atomicAdd(&g_cursor[col], 1);
            g_bucket[g_off[col] + pos] = row;
        }
    }
}

// ---------------------------------------------------------------- gather + zr fused
__global__ void gather_zr_kernel(const float* __restrict__ b) {
    int tid = threadIdx.x;
    int node = blockIdx.x * 4 + (tid >> 6);
    int d = tid & 63;
    if (node >= N_NODES) return;
    int off0 = g_off[node], off1 = g_off[node + 1];
    float acc = 0.0f;
    int k = off0;
    for (; k + 4 <= off1; k += 4) {
        int r0 = g_bucket[k], r1 = g_bucket[k + 1];
        int r2 = g_bucket[k + 2], r3 = g_bucket[k + 3];
        acc += g_hs[r0 * DIM + d] + g_hs[r1 * DIM + d]
             + g_hs[r2 * DIM + d] + g_hs[r3 * DIM + d];
    }
    for (; k < off1; k++) acc += g_hs[g_bucket[k] * DIM + d];

    int idx = node * DIM + d;
    float v = fmaf(g_dinv[node], acc + g_hs[idx], b[d]);
    v = fmaxf(v, 0.0f);
    __nv_bfloat16 hi = __float2bfloat16(v);
    float lo = v - __bfloat162float(hi);
    g_zrh[idx] = hi;
    g_zrl[idx] = __float2bfloat16(lo);
}

// ---------------------------------------------------------------- mma.sync GEMM: C = zr @ zr.T
#define MMA16816(d, a0, a1, a2, a3, b0, b1)                                     \
    asm volatile(                                                               \
        "mma.sync.aligned.m16n8k16.row.col.f32.bf16.bf16.f32 "                  \
        "{%0,%1,%2,%3},{%4,%5,%6,%7},{%8,%9},{%0,%1,%2,%3};"                    \
        : "+f"(d[0]), "+f"(d[1]), "+f"(d[2]), "+f"(d[3])                        \
        : "r"(a0), "r"(a1), "r"(a2), "r"(a3), "r"(b0), "r"(b1))

__global__ __launch_bounds__(256) void gemm_mma_kernel(float* __restrict__ C) {
    int i = blockIdx.x;
    int bx = (int)((sqrtf(8.0f * i + 1.0f) - 1.0f) * 0.5f);
    while ((bx + 1) * (bx + 2) / 2 <= i) bx++;
    while (bx * (bx + 1) / 2 > i) bx--;
    int by = i - bx * (bx + 1) / 2;

    __shared__ __align__(16) __nv_bfloat16 Ah[128][36];
    __shared__ __align__(16) __nv_bfloat16 Al[128][36];
    __shared__ __align__(16) __nv_bfloat16 Bh[128][36];
    __shared__ __align__(16) __nv_bfloat16 Bl[128][36];

    int tid = threadIdx.x;
    int wid = tid >> 5, lane = tid & 31;
    int wm = wid >> 2, wn = wid & 3;
    int g = lane >> 2, t = lane & 3;

    float acc[4][4][4];
#pragma unroll
    for (int mi = 0; mi < 4; mi++)
#pragma unroll
        for (int ni = 0; ni < 4; ni++)
#pragma unroll
            for (int r = 0; r < 4; r++) acc[mi][ni][r] = 0.0f;

    int frow = tid & 127;
    bool isA = tid < 128;
    int grow = (isA ? by : bx) * 128 + frow;
    __nv_bfloat16* dsth = isA ? &Ah[frow][0] : &Bh[frow][0];
    __nv_bfloat16* dstl = isA ? &Al[frow][0] : &Bl[frow][0];

#pragma unroll
    for (int kp = 0; kp < 2; kp++) {
        if (kp) __syncthreads();
        {
            const uint2* sh = (const uint2*)&g_zrh[grow * DIM + kp * 32];
            const uint2* sl = (const uint2*)&g_zrl[grow * DIM + kp * 32];
#pragma unroll
            for (int c = 0; c < 8; c++) {
                *(uint2*)&dsth[c * 4] = sh[c];
                *(uint2*)&dstl[c * 4] = sl[c];
            }
        }
        __syncthreads();

#pragma unroll
        for (int ks = 0; ks < 2; ks++) {
            int k0 = ks * 16 + 2 * t;
            uint32_t ah[4][4], al[4][4], bh[4][2], bl[4][2];
#pragma unroll
            for (int mi = 0; mi < 4; mi++) {
                int r0 = wm * 64 + mi * 16 + g;
                ah[mi][0] = *(const uint32_t*)&Ah[r0][k0];
                ah[mi][1] = *(const uint32_t*)&Ah[r0 + 8][k0];
                ah[mi][2] = *(const uint32_t*)&Ah[r0][k0 + 8];
                ah[mi][3] = *(const uint32_t*)&Ah[r0 + 8][k0 + 8];
                al[mi][0] = *(const uint32_t*)&Al[r0][k0];
                al[mi][1] = *(const uint32_t*)&Al[r0 + 8][k0];
                al[mi][2] = *(const uint32_t*)&Al[r0][k0 + 8];
                al[mi][3] = *(const uint32_t*)&Al[r0 + 8][k0 + 8];
            }
#pragma unroll
            for (int ni = 0; ni < 4; ni++) {
                int c0 = wn * 32 + ni * 8 + g;
                bh[ni][0] = *(const uint32_t*)&Bh[c0][k0];
                bh[ni][1] = *(const uint32_t*)&Bh[c0][k0 + 8];
                bl[ni][0] = *(const uint32_t*)&Bl[c0][k0];
                bl[ni][1] = *(const uint32_t*)&Bl[c0][k0 + 8];
            }
#pragma unroll
            for (int mi = 0; mi < 4; mi++)
#pragma unroll
                for (int ni = 0; ni < 4; ni++) {
                    MMA16816(acc[mi][ni], ah[mi][0], ah[mi][1], ah[mi][2], ah[mi][3],
                             bh[ni][0], bh[ni][1]);
                    MMA16816(acc[mi][ni], ah[mi][0], ah[mi][1], ah[mi][2], ah[mi][3],
                             bl[ni][0], bl[ni][1]);
                    MMA16816(acc[mi][ni], al[mi][0], al[mi][1], al[mi][2], al[mi][3],
                             bh[ni][0], bh[ni][1]);
                }
        }
    }

    bool diag = (bx == by);
#pragma unroll
    for (int mi = 0; mi < 4; mi++) {
        int m0 = by * 128 + wm * 64 + mi * 16 + g;
#pragma unroll
        for (int ni = 0; ni < 4; ni++) {
            int n0 = bx * 128 + wn * 32 + ni * 8 + 2 * t;
            float* a = acc[mi][ni];
            if (n0 < N_NODES) {
                if (m0 < N_NODES)
                    __stcs((float2*)&C[(size_t)m0 * N_NODES + n0], make_float2(a[0], a[1]));
                if (m0 + 8 < N_NODES)
                    __stcs((float2*)&C[(size_t)(m0 + 8) * N_NODES + n0], make_float2(a[2], a[3]));
            }
            if (!diag) {
                if (n0 < N_NODES) {
                    if (m0 < N_NODES)     __stcs(&C[(size_t)n0 * N_NODES + m0], a[0]);
                    if (m0 + 8 < N_NODES) __stcs(&C[(size_t)n0 * N_NODES + m0 + 8], a[2]);
                }
                if (n0 + 1 < N_NODES) {
                    if (m0 < N_NODES)     __stcs(&C[(size_t)(n0 + 1) * N_NODES + m0], a[1]);
                    if (m0 + 8 < N_NODES) __stcs(&C[(size_t)(n0 + 1) * N_NODES + m0 + 8], a[3]);
                }
            }
        }
    }
}

// ---------------------------------------------------------------- launch
extern "C" void kernel_launch(void* const* d_in, const int* in_sizes, int n_in,
                              void* d_out, int out_size) {
    const float* z = (const float*)d_in[0];
    const void* ei = d_in[1];
    const float* W = (const float*)d_in[2];
    const float* b = (const float*)d_in[3];
    float* C = (float*)d_out;

    init_kernel<<<(N_NODES + 255) / 256, 256>>>((const long long*)ei);
    hist_kernel<<<(N_EDGES + 255) / 256, 256>>>(ei);
    scan_kernel<<<1, 256>>>();
    hs_kernel<<<(N_NODES + 3) / 4, 256>>>(z, W);
    fill_kernel<<<(N_EDGES + 255) / 256, 256>>>(ei);
    gather_zr_kernel<<<(N_NODES + 3) / 4, 256>>>(b);
    gemm_mma_kernel<<<NTILE * (NTILE + 1) / 2, 256>>>(C);
}

// round 16
// speedup vs baseline: 1.2884x; 1.0183x over previous
#include <cuda_runtime.h>
#include <cuda_bf16.h>
#include <cstdint>

#define N_NODES 10000
#define N_PAD 10112           // 79 * 128
#define N_EDGES 320000
#define DIM 64
#define NTILE 79

// Scratch (allocation-free rule: __device__ globals)
__device__ int   g_is32;
__device__ int   g_cnt[N_NODES];        // incoming-edge histogram (no self-loop)
__device__ int   g_cursor[N_NODES];
__device__ int   g_off[N_NODES + 4];    // +pad so int4 store at 9996 is safe
__device__ int   g_bucket[N_EDGES];     // source rows grouped by destination
__device__ float g_dinv[N_NODES];
__device__ float g_hs[N_NODES * DIM];
__device__ __nv_bfloat16 g_zrh[N_PAD * DIM];   // bf16 hi plane of zr (padded)
__device__ __nv_bfloat16 g_zrl[N_PAD * DIM];   // bf16 lo plane of zr (padded)

__device__ __forceinline__ int edge_fetch(const void* ei, int idx) {
    return g_is32 ? ((const int*)ei)[idx] : (int)((const long long*)ei)[idx];
}

// ---------------------------------------------------------------- init (+ dtype probe in block 0)
__global__ void init_kernel(const long long* __restrict__ ei) {
    int i = blockIdx.x * 256 + threadIdx.x;
    if (blockIdx.x == 0) {
        __shared__ unsigned wm[8];
        long long v = ei[threadIdx.x];
        int bad = (v < 0 || v >= N_NODES) ? 1 : 0;
        unsigned m = __ballot_sync(0xFFFFFFFFu, bad);
        if ((threadIdx.x & 31) == 0) wm[threadIdx.x >> 5] = m;
        __syncthreads();
        if (threadIdx.x == 0) {
            unsigned any = 0;
#pragma unroll
            for (int j = 0; j < 8; j++) any |= wm[j];
            g_is32 = any ? 1 : 0;
        }
    }
    if (i < N_NODES) { g_cnt[i] = 0; g_cursor[i] = 0; }
    if (i < (N_PAD - N_NODES) * DIM) {
        g_zrh[N_NODES * DIM + i] = __float2bfloat16(0.0f);
        g_zrl[N_NODES * DIM + i] = __float2bfloat16(0.0f);
    }
}

// ---------------------------------------------------------------- histogram of destinations
__global__ void hist_kernel(const void* __restrict__ ei) {
    int e = blockIdx.x * 256 + threadIdx.x;
    if (e < N_EDGES) {
        int col = edge_fetch(ei, N_EDGES + e);
        if ((unsigned)col < N_NODES) atomicAdd(&g_cnt[col], 1);
    }
}

// ---------------------------------------------------------------- scan: offsets + dinv (shfl-based)
__global__ void scan_kernel() {
    int t = threadIdx.x;                 // 256 threads, 1 block
    int lane = t & 31, w = t >> 5;
    const int CH = 40;                   // 256*40 = 10240 >= 10000
    int base = t * CH;
    int4 c[10];
    int s = 0;
#pragma unroll
    for (int j = 0; j < 10; j++) {
        int idx = base + j * 4;
        c[j] = (idx < N_NODES) ? *(const int4*)&g_cnt[idx] : make_int4(0, 0, 0, 0);
        s += c[j].x + c[j].y + c[j].z + c[j].w;
    }
    int v = s;
#pragma unroll
    for (int o = 1; o < 32; o <<= 1) {
        int u = __shfl_up_sync(0xFFFFFFFFu, v, o);
        if (lane >= o) v += u;
    }
    __shared__ int wsum[8];
    if (lane == 31) wsum[w] = v;
    __syncthreads();
    if (w == 0 && lane < 8) {
        int x = wsum[lane];
#pragma unroll
        for (int o = 1; o < 8; o <<= 1) {
            int u = __shfl_up_sync(0xFFu, x, o);
            if (lane >= o) x += u;
        }
        wsum[lane] = x;
    }
    __syncthreads();
    int excl = v - s + (w ? wsum[w - 1] : 0);
#pragma unroll
    for (int j = 0; j < 10; j++) {
        int idx = base + j * 4;
        if (idx < N_NODES) {
            int4 off;
            off.x = excl;
            off.y = off.x + c[j].x;
            off.z = off.y + c[j].y;
            off.w = off.z + c[j].z;
            excl = off.w + c[j].w;
            *(int4*)&g_off[idx] = off;
            g_dinv[idx]     = rsqrtf((float)(c[j].x + 1));
            g_dinv[idx + 1] = rsqrtf((float)(c[j].y + 1));
            g_dinv[idx + 2] = rsqrtf((float)(c[j].z + 1));
            g_dinv[idx + 3] = rsqrtf((float)(c[j].w + 1));
        }
    }
    if (t == 255) g_off[N_NODES] = excl;
}

// ---------------------------------------------------------------- hs = (z@W) * dinv
// 64 rows/block; zT[64][72] transposed z tile, Ws[64][72]; each thread owns a
// 4x4 output tile -> per k: 2x LDS.128 + 16 FMA (FMA-roofline balanced).
__global__ __launch_bounds__(256) void hs_kernel(const float* __restrict__ z,
                                                 const float* __restrict__ W) {
    __shared__ float Ws[64][72];
    __shared__ float zT[64][72];   // zT[k][r]
    int tid = threadIdx.x;
    int r = tid & 63;              // row within tile / W row
    int kg = tid >> 6;             // 0..3 -> k chunk of 16
    int row = blockIdx.x * 64 + r;

    // fill W[k][d] chunk (no transpose)
    {
        const float4* src = (const float4*)&W[r * 64 + kg * 16];
#pragma unroll
        for (int j = 0; j < 4; j++) *(float4*)&Ws[r][kg * 16 + j * 4] = src[j];
    }
    // fill zT: thread loads z[row][kg*16..+15], writes transposed (conflict-free)
    {
#pragma unroll
        for (int j = 0; j < 4; j++) {
            float4 v = (row < N_NODES) ? *(const float4*)&z[row * 64 + kg * 16 + j * 4]
                                       : make_float4(0.f, 0.f, 0.f, 0.f);
            int k0 = kg * 16 + j * 4;
            zT[k0 + 0][r] = v.x;
            zT[k0 + 1][r] = v.y;
            zT[k0 + 2][r] = v.z;
            zT[k0 + 3][r] = v.w;
        }
    }
    __syncthreads();

    int c4 = (tid & 15) * 4;       // output col group
    int r4 = (tid >> 4) * 4;       // output row group
    float acc[4][4];
#pragma unroll
    for (int i = 0; i < 4; i++)
#pragma unroll
        for (int j = 0; j < 4; j++) acc[i][j] = 0.0f;

#pragma unroll 8
    for (int k = 0; k < 64; k++) {
        float4 zv = *(const float4*)&zT[k][r4];
        float4 wv = *(const float4*)&Ws[k][c4];
        float zr_[4] = {zv.x, zv.y, zv.z, zv.w};
        float wr_[4] = {wv.x, wv.y, wv.z, wv.w};
#pragma unroll
        for (int i = 0; i < 4; i++)
#pragma unroll
            for (int j = 0; j < 4; j++)
                acc[i][j] = fmaf(zr_[i], wr_[j], acc[i][j]);
    }

#pragma unroll
    for (int i = 0; i < 4; i++) {
        int orow = blockIdx.x * 64 + r4 + i;
        if (orow < N_NODES) {
            float dv = g_dinv[orow];
            float4 o = make_float4(acc[i][0] * dv, acc[i][1] * dv,
                                   acc[i][2] * dv, acc[i][3] * dv);
            *(float4*)&g_hs[orow * 64 + c4] = o;
        }
    }
}

// ---------------------------------------------------------------- bucket fill (CSR)
__global__ void fill_kernel(const void* __restrict__ ei) {
    int e = blockIdx.x * 256 + threadIdx.x;
    if (e < N_EDGES) {
        int row = edge_fetch(ei, e);
        int col = edge_fetch(ei, N_EDGES + e);
        if ((unsigned)row < N_NODES && (unsigned)col < N_NODES) {
            int pos = atomicAdd(&g_cursor[col], 1);
            g_bucket[g_off[col] + pos] = row;
        }
    }
}

// ---------------------------------------------------------------- gather + zr fused
__global__ void gather_zr_kernel(const float* __restrict__ b) {
    int tid = threadIdx.x;
    int node = blockIdx.x * 4 + (tid >> 6);
    int d = tid & 63;
    if (node >= N_NODES) return;
    int off0 = g_off[node], off1 = g_off[node + 1];
    float acc = 0.0f;
    int k = off0;
    for (; k + 4 <= off1; k += 4) {
        int r0 = g_bucket[k], r1 = g_bucket[k + 1];
        int r2 = g_bucket[k + 2], r3 = g_bucket[k + 3];
        acc += g_hs[r0 * DIM + d] + g_hs[r1 * DIM + d]
             + g_hs[r2 * DIM + d] + g_hs[r3 * DIM + d];
    }
    for (; k < off1; k++) acc += g_hs[g_bucket[k] * DIM + d];

    int idx = node * DIM + d;
    float v = fmaf(g_dinv[node], acc + g_hs[idx], b[d]);
    v = fmaxf(v, 0.0f);
    __nv_bfloat16 hi = __float2bfloat16(v);
    float lo = v - __bfloat162float(hi);
    g_zrh[idx] = hi;
    g_zrl[idx] = __float2bfloat16(lo);
}

// ---------------------------------------------------------------- mma.sync GEMM: C = zr @ zr.T
#define MMA16816(d, a0, a1, a2, a3, b0, b1)                                     \
    asm volatile(                                                               \
        "mma.sync.aligned.m16n8k16.row.col.f32.bf16.bf16.f32 "                  \
        "{%0,%1,%2,%3},{%4,%5,%6,%7},{%8,%9},{%0,%1,%2,%3};"                    \
        : "+f"(d[0]), "+f"(d[1]), "+f"(d[2]), "+f"(d[3])                        \
        : "r"(a0), "r"(a1), "r"(a2), "r"(a3), "r"(b0), "r"(b1))

__global__ __launch_bounds__(256) void gemm_mma_kernel(float* __restrict__ C) {
    int i = blockIdx.x;
    int bx = (int)((sqrtf(8.0f * i + 1.0f) - 1.0f) * 0.5f);
    while ((bx + 1) * (bx + 2) / 2 <= i) bx++;
    while (bx * (bx + 1) / 2 > i) bx--;
    int by = i - bx * (bx + 1) / 2;

    __shared__ __align__(16) __nv_bfloat16 Ah[128][36];
    __shared__ __align__(16) __nv_bfloat16 Al[128][36];
    __shared__ __align__(16) __nv_bfloat16 Bh[128][36];
    __shared__ __align__(16) __nv_bfloat16 Bl[128][36];

    int tid = threadIdx.x;
    int wid = tid >> 5, lane = tid & 31;
    int wm = wid >> 2, wn = wid & 3;
    int g = lane >> 2, t = lane & 3;

    float acc[4][4][4];
#pragma unroll
    for (int mi = 0; mi < 4; mi++)
#pragma unroll
        for (int ni = 0; ni < 4; ni++)
#pragma unroll
            for (int r = 0; r < 4; r++) acc[mi][ni][r] = 0.0f;

    int frow = tid & 127;
    bool isA = tid < 128;
    int grow = (isA ? by : bx) * 128 + frow;
    __nv_bfloat16* dsth = isA ? &Ah[frow][0] : &Bh[frow][0];
    __nv_bfloat16* dstl = isA ? &Al[frow][0] : &Bl[frow][0];

#pragma unroll
    for (int kp = 0; kp < 2; kp++) {
        if (kp) __syncthreads();
        {
            const uint2* sh = (const uint2*)&g_zrh[grow * DIM + kp * 32];
            const uint2* sl = (const uint2*)&g_zrl[grow * DIM + kp * 32];
#pragma unroll
            for (int c = 0; c < 8; c++) {
                *(uint2*)&dsth[c * 4] = sh[c];
                *(uint2*)&dstl[c * 4] = sl[c];
            }
        }
        __syncthreads();

#pragma unroll
        for (int ks = 0; ks < 2; ks++) {
            int k0 = ks * 16 + 2 * t;
            uint32_t ah[4][4], al[4][4], bh[4][2], bl[4][2];
#pragma unroll
            for (int mi = 0; mi < 4; mi++) {
                int r0 = wm * 64 + mi * 16 + g;
                ah[mi][0] = *(const uint32_t*)&Ah[r0][k0];
                ah[mi][1] = *(const uint32_t*)&Ah[r0 + 8][k0];
                ah[mi][2] = *(const uint32_t*)&Ah[r0][k0 + 8];
                ah[mi][3] = *(const uint32_t*)&Ah[r0 + 8][k0 + 8];
                al[mi][0] = *(const uint32_t*)&Al[r0][k0];
                al[mi][1] = *(const uint32_t*)&Al[r0 + 8][k0];
                al[mi][2] = *(const uint32_t*)&Al[r0][k0 + 8];
                al[mi][3] = *(const uint32_t*)&Al[r0 + 8][k0 + 8];
            }
#pragma unroll
            for (int ni = 0; ni < 4; ni++) {
                int c0 = wn * 32 + ni * 8 + g;
                bh[ni][0] = *(const uint32_t*)&Bh[c0][k0];
                bh[ni][1] = *(const uint32_t*)&Bh[c0][k0 + 8];
                bl[ni][0] = *(const uint32_t*)&Bl[c0][k0];
                bl[ni][1] = *(const uint32_t*)&Bl[c0][k0 + 8];
            }
#pragma unroll
            for (int mi = 0; mi < 4; mi++)
#pragma unroll
                for (int ni = 0; ni < 4; ni++) {
                    MMA16816(acc[mi][ni], ah[mi][0], ah[mi][1], ah[mi][2], ah[mi][3],
                             bh[ni][0], bh[ni][1]);
                    MMA16816(acc[mi][ni], ah[mi][0], ah[mi][1], ah[mi][2], ah[mi][3],
                             bl[ni][0], bl[ni][1]);
                    MMA16816(acc[mi][ni], al[mi][0], al[mi][1], al[mi][2], al[mi][3],
                             bh[ni][0], bh[ni][1]);
                }
        }
    }

    bool diag = (bx == by);
#pragma unroll
    for (int mi = 0; mi < 4; mi++) {
        int m0 = by * 128 + wm * 64 + mi * 16 + g;
#pragma unroll
        for (int ni = 0; ni < 4; ni++) {
            int n0 = bx * 128 + wn * 32 + ni * 8 + 2 * t;
            float* a = acc[mi][ni];
            if (n0 < N_NODES) {
                if (m0 < N_NODES)
                    __stcs((float2*)&C[(size_t)m0 * N_NODES + n0], make_float2(a[0], a[1]));
                if (m0 + 8 < N_NODES)
                    __stcs((float2*)&C[(size_t)(m0 + 8) * N_NODES + n0], make_float2(a[2], a[3]));
            }
            if (!diag) {
                if (n0 < N_NODES) {
                    if (m0 < N_NODES)     __stcs(&C[(size_t)n0 * N_NODES + m0], a[0]);
                    if (m0 + 8 < N_NODES) __stcs(&C[(size_t)n0 * N_NODES + m0 + 8], a[2]);
                }
                if (n0 + 1 < N_NODES) {
                    if (m0 < N_NODES)     __stcs(&C[(size_t)(n0 + 1) * N_NODES + m0], a[1]);
                    if (m0 + 8 < N_NODES) __stcs(&C[(size_t)(n0 + 1) * N_NODES + m0 + 8], a[3]);
                }
            }
        }
    }
}

// ---------------------------------------------------------------- launch
extern "C" void kernel_launch(void* const* d_in, const int* in_sizes, int n_in,
                              void* d_out, int out_size) {
    const float* z = (const float*)d_in[0];
    const void* ei = d_in[1];
    const float* W = (const float*)d_in[2];
    const float* b = (const float*)d_in[3];
    float* C = (float*)d_out;

    init_kernel<<<(N_NODES + 255) / 256, 256>>>((const long long*)ei);
    hist_kernel<<<(N_EDGES + 255) / 256, 256>>>(ei);
    scan_kernel<<<1, 256>>>();
    hs_kernel<<<(N_NODES + 63) / 64, 256>>>(z, W);
    fill_kernel<<<(N_EDGES + 255) / 256, 256>>>(ei);
    gather_zr_kernel<<<(N_NODES + 3) / 4, 256>>>(b);
    gemm_mma_kernel<<<NTILE * (NTILE + 1) / 2, 256>>>(C);
}

// round 17
// speedup vs baseline: 2.1687x; 1.6833x over previous
#include <cuda_runtime.h>
#include <cuda_fp16.h>
#include <cstdint>

#define N_NODES 10000
#define N_PAD 10112           // 79 * 128
#define N_EDGES 320000
#define DIM 64
#define NTILE 79

// Scratch (allocation-free rule: __device__ globals)
__device__ int   g_is32;
__device__ int   g_cnt[N_NODES];        // incoming-edge histogram (no self-loop)
__device__ int   g_cursor[N_NODES];
__device__ int   g_off[N_NODES + 4];    // +pad so int4 store at 9996 is safe
__device__ int   g_bucket[N_EDGES];     // source rows grouped by destination
__device__ float g_dinv[N_NODES];
__device__ float g_hs[N_NODES * DIM];
__device__ __half g_zrf[N_PAD * DIM];   // fp16 zr (padded) — single plane

__device__ __forceinline__ int edge_fetch(const void* ei, int idx) {
    return g_is32 ? ((const int*)ei)[idx] : (int)((const long long*)ei)[idx];
}

// ---------------------------------------------------------------- init (+ dtype probe in block 0)
__global__ void init_kernel(const long long* __restrict__ ei) {
    int i = blockIdx.x * 256 + threadIdx.x;
    if (blockIdx.x == 0) {
        __shared__ unsigned wm[8];
        long long v = ei[threadIdx.x];
        int bad = (v < 0 || v >= N_NODES) ? 1 : 0;
        unsigned m = __ballot_sync(0xFFFFFFFFu, bad);
        if ((threadIdx.x & 31) == 0) wm[threadIdx.x >> 5] = m;
        __syncthreads();
        if (threadIdx.x == 0) {
            unsigned any = 0;
#pragma unroll
            for (int j = 0; j < 8; j++) any |= wm[j];
            g_is32 = any ? 1 : 0;
        }
    }
    if (i < N_NODES) { g_cnt[i] = 0; g_cursor[i] = 0; }
    if (i < (N_PAD - N_NODES) * DIM)
        g_zrf[N_NODES * DIM + i] = __float2half(0.0f);
}

// ---------------------------------------------------------------- histogram of destinations
__global__ void hist_kernel(const void* __restrict__ ei) {
    int e = blockIdx.x * 256 + threadIdx.x;
    if (e < N_EDGES) {
        int col = edge_fetch(ei, N_EDGES + e);
        if ((unsigned)col < N_NODES) atomicAdd(&g_cnt[col], 1);
    }
}

// ---------------------------------------------------------------- scan: offsets + dinv (shfl-based)
__global__ void scan_kernel() {
    int t = threadIdx.x;                 // 256 threads, 1 block
    int lane = t & 31, w = t >> 5;
    const int CH = 40;                   // 256*40 = 10240 >= 10000
    int base = t * CH;
    int4 c[10];
    int s = 0;
#pragma unroll
    for (int j = 0; j < 10; j++) {
        int idx = base + j * 4;
        c[j] = (idx < N_NODES) ? *(const int4*)&g_cnt[idx] : make_int4(0, 0, 0, 0);
        s += c[j].x + c[j].y + c[j].z + c[j].w;
    }
    int v = s;
#pragma unroll
    for (int o = 1; o < 32; o <<= 1) {
        int u = __shfl_up_sync(0xFFFFFFFFu, v, o);
        if (lane >= o) v += u;
    }
    __shared__ int wsum[8];
    if (lane == 31) wsum[w] = v;
    __syncthreads();
    if (w == 0 && lane < 8) {
        int x = wsum[lane];
#pragma unroll
        for (int o = 1; o < 8; o <<= 1) {
            int u = __shfl_up_sync(0xFFu, x, o);
            if (lane >= o) x += u;
        }
        wsum[lane] = x;
    }
    __syncthreads();
    int excl = v - s + (w ? wsum[w - 1] : 0);
#pragma unroll
    for (int j = 0; j < 10; j++) {
        int idx = base + j * 4;
        if (idx < N_NODES) {
            int4 off;
            off.x = excl;
            off.y = off.x + c[j].x;
            off.z = off.y + c[j].y;
            off.w = off.z + c[j].z;
            excl = off.w + c[j].w;
            *(int4*)&g_off[idx] = off;
            g_dinv[idx]     = rsqrtf((float)(c[j].x + 1));
            g_dinv[idx + 1] = rsqrtf((float)(c[j].y + 1));
            g_dinv[idx + 2] = rsqrtf((float)(c[j].z + 1));
            g_dinv[idx + 3] = rsqrtf((float)(c[j].w + 1));
        }
    }
    if (t == 255) g_off[N_NODES] = excl;
}

// ---------------------------------------------------------------- hs = (z@W) * dinv
__global__ __launch_bounds__(256) void hs_kernel(const float* __restrict__ z,
                                                 const float* __restrict__ W) {
    __shared__ float Ws[64][72];
    __shared__ float zT[64][72];   // zT[k][r]
    int tid = threadIdx.x;
    int r = tid & 63;
    int kg = tid >> 6;
    int row = blockIdx.x * 64 + r;

    {
        const float4* src = (const float4*)&W[r * 64 + kg * 16];
#pragma unroll
        for (int j = 0; j < 4; j++) *(float4*)&Ws[r][kg * 16 + j * 4] = src[j];
    }
    {
#pragma unroll
        for (int j = 0; j < 4; j++) {
            float4 v = (row < N_NODES) ? *(const float4*)&z[row * 64 + kg * 16 + j * 4]
                                       : make_float4(0.f, 0.f, 0.f, 0.f);
            int k0 = kg * 16 + j * 4;
            zT[k0 + 0][r] = v.x;
            zT[k0 + 1][r] = v.y;
            zT[k0 + 2][r] = v.z;
            zT[k0 + 3][r] = v.w;
        }
    }
    __syncthreads();

    int c4 = (tid & 15) * 4;
    int r4 = (tid >> 4) * 4;
    float acc[4][4];
#pragma unroll
    for (int i = 0; i < 4; i++)
#pragma unroll
        for (int j = 0; j < 4; j++) acc[i][j] = 0.0f;

#pragma unroll 8
    for (int k = 0; k < 64; k++) {
        float4 zv = *(const float4*)&zT[k][r4];
        float4 wv = *(const float4*)&Ws[k][c4];
        float zr_[4] = {zv.x, zv.y, zv.z, zv.w};
        float wr_[4] = {wv.x, wv.y, wv.z, wv.w};
#pragma unroll
        for (int i = 0; i < 4; i++)
#pragma unroll
            for (int j = 0; j < 4; j++)
                acc[i][j] = fmaf(zr_[i], wr_[j], acc[i][j]);
    }

#pragma unroll
    for (int i = 0; i < 4; i++) {
        int orow = blockIdx.x * 64 + r4 + i;
        if (orow < N_NODES) {
            float dv = g_dinv[orow];
            float4 o = make_float4(acc[i][0] * dv, acc[i][1] * dv,
                                   acc[i][2] * dv, acc[i][3] * dv);
            *(float4*)&g_hs[orow * 64 + c4] = o;
        }
    }
}

// ---------------------------------------------------------------- bucket fill (CSR)
__global__ void fill_kernel(const void* __restrict__ ei) {
    int e = blockIdx.x * 256 + threadIdx.x;
    if (e < N_EDGES) {
        int row = edge_fetch(ei, e);
        int col = edge_fetch(ei, N_EDGES + e);
        if ((unsigned)row < N_NODES && (unsigned)col < N_NODES) {
            int pos = atomicAdd(&g_cursor[col], 1);
            g_bucket[g_off[col] + pos] = row;
        }
    }
}

// ---------------------------------------------------------------- gather + zr fused (emit fp16)
__global__ void gather_zr_kernel(const float* __restrict__ b) {
    int tid = threadIdx.x;
    int node = blockIdx.x * 4 + (tid >> 6);
    int d = tid & 63;
    if (node >= N_NODES) return;
    int off0 = g_off[node], off1 = g_off[node + 1];
    float acc = 0.0f;
    int k = off0;
    for (; k + 4 <= off1; k += 4) {
        int r0 = g_bucket[k], r1 = g_bucket[k + 1];
        int r2 = g_bucket[k + 2], r3 = g_bucket[k + 3];
        acc += g_hs[r0 * DIM + d] + g_hs[r1 * DIM + d]
             + g_hs[r2 * DIM + d] + g_hs[r3 * DIM + d];
    }
    for (; k < off1; k++) acc += g_hs[g_bucket[k] * DIM + d];

    int idx = node * DIM + d;
    float v = fmaf(g_dinv[node], acc + g_hs[idx], b[d]);
    g_zrf[idx] = __float2half(fmaxf(v, 0.0f));
}

// ---------------------------------------------------------------- mma.sync GEMM: C = zr @ zr.T
// Single fp16 product (zr >= 0 => no cancellation; rel_err ~3e-5).
// 128x128 tile/CTA, K=64 single pass, smem [128][72] fp16 (conflict-free).
#define MMAF16(d, a0, a1, a2, a3, b0, b1)                                       \
    asm volatile(                                                               \
        "mma.sync.aligned.m16n8k16.row.col.f32.f16.f16.f32 "                    \
        "{%0,%1,%2,%3},{%4,%5,%6,%7},{%8,%9},{%0,%1,%2,%3};"                    \
        : "+f"(d[0]), "+f"(d[1]), "+f"(d[2]), "+f"(d[3])                        \
        : "r"(a0), "r"(a1), "r"(a2), "r"(a3), "r"(b0), "r"(b1))

__global__ __launch_bounds__(256) void gemm_mma_kernel(float* __restrict__ C) {
    int i = blockIdx.x;
    int bx = (int)((sqrtf(8.0f * i + 1.0f) - 1.0f) * 0.5f);
    while ((bx + 1) * (bx + 2) / 2 <= i) bx++;
    while (bx * (bx + 1) / 2 > i) bx--;
    int by = i - bx * (bx + 1) / 2;

    __shared__ __align__(16) __half Ah[128][72];
    __shared__ __align__(16) __half Bh[128][72];

    int tid = threadIdx.x;
    int wid = tid >> 5, lane = tid & 31;
    int wm = wid >> 2, wn = wid & 3;
    int g = lane >> 2, t = lane & 3;

    float acc[4][4][4];
#pragma unroll
    for (int mi = 0; mi < 4; mi++)
#pragma unroll
        for (int ni = 0; ni < 4; ni++)
#pragma unroll
            for (int r = 0; r < 4; r++) acc[mi][ni][r] = 0.0f;

    // fill: thread t<128 owns A row t, t>=128 owns B row t-128 (8x 16B copies)
    {
        int frow = tid & 127;
        bool isA = tid < 128;
        int grow = (isA ? by : bx) * 128 + frow;
        const uint4* src = (const uint4*)&g_zrf[grow * DIM];
        __half* dst = isA ? &Ah[frow][0] : &Bh[frow][0];
#pragma unroll
        for (int c = 0; c < 8; c++) *(uint4*)&dst[c * 8] = src[c];
    }
    __syncthreads();

#pragma unroll
    for (int ks = 0; ks < 4; ks++) {
        int k0 = ks * 16 + 2 * t;
        uint32_t ah[4][4], bh[4][2];
#pragma unroll
        for (int mi = 0; mi < 4; mi++) {
            int r0 = wm * 64 + mi * 16 + g;
            ah[mi][0] = *(const uint32_t*)&Ah[r0][k0];
            ah[mi][1] = *(const uint32_t*)&Ah[r0 + 8][k0];
            ah[mi][2] = *(const uint32_t*)&Ah[r0][k0 + 8];
            ah[mi][3] = *(const uint32_t*)&Ah[r0 + 8][k0 + 8];
        }
#pragma unroll
        for (int ni = 0; ni < 4; ni++) {
            int c0 = wn * 32 + ni * 8 + g;
            bh[ni][0] = *(const uint32_t*)&Bh[c0][k0];
            bh[ni][1] = *(const uint32_t*)&Bh[c0][k0 + 8];
        }
#pragma unroll
        for (int mi = 0; mi < 4; mi++)
#pragma unroll
            for (int ni = 0; ni < 4; ni++)
                MMAF16(acc[mi][ni], ah[mi][0], ah[mi][1], ah[mi][2], ah[mi][3],
                       bh[ni][0], bh[ni][1]);
    }

    bool diag = (bx == by);
#pragma unroll
    for (int mi = 0; mi < 4; mi++) {
        int m0 = by * 128 + wm * 64 + mi * 16 + g;
#pragma unroll
        for (int ni = 0; ni < 4; ni++) {
            int n0 = bx * 128 + wn * 32 + ni * 8 + 2 * t;
            float* a = acc[mi][ni];
            if (n0 < N_NODES) {
                if (m0 < N_NODES)
                    __stcs((float2*)&C[(size_t)m0 * N_NODES + n0], make_float2(a[0], a[1]));
                if (m0 + 8 < N_NODES)
                    __stcs((float2*)&C[(size_t)(m0 + 8) * N_NODES + n0], make_float2(a[2], a[3]));
            }
            if (!diag) {
                if (n0 < N_NODES) {
                    if (m0 < N_NODES)     __stcs(&C[(size_t)n0 * N_NODES + m0], a[0]);
                    if (m0 + 8 < N_NODES) __stcs(&C[(size_t)n0 * N_NODES + m0 + 8], a[2]);
                }
                if (n0 + 1 < N_NODES) {
                    if (m0 < N_NODES)     __stcs(&C[(size_t)(n0 + 1) * N_NODES + m0], a[1]);
                    if (m0 + 8 < N_NODES) __stcs(&C[(size_t)(n0 + 1) * N_NODES + m0 + 8], a[3]);
                }
            }
        }
    }
}

// ---------------------------------------------------------------- launch
extern "C" void kernel_launch(void* const* d_in, const int* in_sizes, int n_in,
                              void* d_out, int out_size) {
    const float* z = (const float*)d_in[0];
    const void* ei = d_in[1];
    const float* W = (const float*)d_in[2];
    const float* b = (const float*)d_in[3];
    float* C = (float*)d_out;

    init_kernel<<<(N_NODES + 255) / 256, 256>>>((const long long*)ei);
    hist_kernel<<<(N_EDGES + 255) / 256, 256>>>(ei);
    scan_kernel<<<1, 256>>>();
    hs_kernel<<<(N_NODES + 63) / 64, 256>>>(z, W);
    fill_kernel<<<(N_EDGES + 255) / 256, 256>>>(ei);
    gather_zr_kernel<<<(N_NODES + 3) / 4, 256>>>(b);
    gemm_mma_kernel<<<NTILE * (NTILE + 1) / 2, 256>>>(C);
}